// round 11
// baseline (speedup 1.0000x reference)
#include <cuda_runtime.h>
#include <cuda_fp16.h>
#include <math.h>
#include <float.h>

#define B_DIM  256
#define T_DIM  150
#define J_DIM  25
#define JCOL   26                       // padded joint columns (25 = dummy)
#define JP     13                       // joint-threads per row: chains j, j+13
#define FEAT   9
#define NACC   7
#define SPLIT  5
#define TCHUNK (T_DIM / SPLIT)          // 30 timesteps per block
#define NPAIR  (TCHUNK / 2)             // 15 timestep-pair rows
#define ACTIVE (NPAIR * JP)             // 195 compute threads
#define TPB    224                      // 7 warps
#define ITEMS  (TCHUNK * J_DIM)         // 750
#define OUTB   (J_DIM * FEAT)           // 225
#define PARTB  (J_DIM * NACC)           // 175

__device__ float    g_scratch[B_DIM][SPLIT][PARTB];
__device__ unsigned g_ticket[B_DIM];    // zero-init; self-resetting

__device__ __forceinline__ float asqrt(float x) {
    float r;
    asm("sqrt.approx.f32 %0, %1;" : "=f"(r) : "f"(x));
    return r;
}

// half2 sorted insert (both lanes independently), branch-free
#define INS4H(g, m0, m1, m2, m3) do {                       \
    __half2 _h;                                             \
    _h = __hmax2(g, m0); m0 = __hmin2(g, m0); g = _h;       \
    _h = __hmax2(g, m1); m1 = __hmin2(g, m1); g = _h;       \
    _h = __hmax2(g, m2); m2 = __hmin2(g, m2); g = _h;       \
    m3 = __hmin2(g, m3);                                    \
} while (0)

__global__ __launch_bounds__(TPB)
void knn_feat_kernel(const float* __restrict__ x, float* __restrict__ out) {
    // packed positions: [pair-row][joint] = {x2, y2, z2, pad}; lanes = (t, t+15)
    __shared__ uint4 sq[NPAIR][JCOL];        // 15*26*16 = 6240 B
    __shared__ float spart[PARTB];
    __shared__ float sfin[PARTB];
    __shared__ bool  s_last;

    const int b   = blockIdx.x;
    const int s   = blockIdx.y;
    const int tid = threadIdx.x;

    // build packed half2 SMEM tile
    const float* xb = x + ((size_t)b * T_DIM + s * TCHUNK) * (J_DIM * 3);
    for (int i = tid; i < ITEMS; i += TPB) {
        int t = i / J_DIM;
        int j = i % J_DIM;
        int pr = t % NPAIR;
        int hi = t / NPAIR;
        __half hx = __float2half_rn(xb[3 * i + 0]);
        __half hy = __float2half_rn(xb[3 * i + 1]);
        __half hz = __float2half_rn(xb[3 * i + 2]);
        __half* base = (__half*)&sq[pr][j];
        base[0 * 2 + hi] = hx;
        base[1 * 2 + hi] = hy;
        base[2 * 2 + hi] = hz;
    }
    if (tid < NPAIR) {
        // dummy joint column: far away -> never selected
        const __half big = __float2half_rn(60000.0f);
        __half* base = (__half*)&sq[tid][J_DIM];
        base[0] = big; base[1] = big;
        base[2] = big; base[3] = big;
        base[4] = big; base[5] = big;
    }
    if (tid < PARTB) spart[tid] = 0.0f;
    __syncthreads();

    if (tid < ACTIVE) {
        const int j1 = tid % JP;             // chain-1 joint (0..12)
        const int pr = tid / JP;             // timestep-pair row (0..14)
        const int j2 = j1 + JP;              // chain-2 joint (13..25; 25=dummy)

        const uint4 P1 = sq[pr][j1];
        const __half2 p1x = *(const __half2*)&P1.x;
        const __half2 p1y = *(const __half2*)&P1.y;
        const __half2 p1z = *(const __half2*)&P1.z;
        const uint4 P2 = sq[pr][j2];
        const __half2 p2x = *(const __half2*)&P2.x;
        const __half2 p2y = *(const __half2*)&P2.y;
        const __half2 p2z = *(const __half2*)&P2.z;

        const unsigned inf_bits = 0x7C007C00u;   // (+inf, +inf)
        const __half2 inf2 = *(const __half2*)&inf_bits;

        __half2 a0 = inf2, a1 = inf2, a2 = inf2, a3 = inf2;   // chain 1
        __half2 c0 = inf2, c1 = inf2, c2 = inf2, c3 = inf2;   // chain 2

#pragma unroll
        for (int j = 0; j < JCOL; ++j) {
            const uint4 Q = sq[pr][j];       // ONE LDS.128 feeds 4 candidates
            const __half2 qx = *(const __half2*)&Q.x;
            const __half2 qy = *(const __half2*)&Q.y;
            const __half2 qz = *(const __half2*)&Q.z;

            const __half2 dx1 = __hsub2(p1x, qx);
            const __half2 dy1 = __hsub2(p1y, qy);
            const __half2 dz1 = __hsub2(p1z, qz);
            __half2 g1 = __hfma2(dx1, dx1, __hfma2(dy1, dy1, __hmul2(dz1, dz1)));
            g1 = (j == j1) ? inf2 : g1;      // mask self

            const __half2 dx2 = __hsub2(p2x, qx);
            const __half2 dy2 = __hsub2(p2y, qy);
            const __half2 dz2 = __hsub2(p2z, qz);
            __half2 g2 = __hfma2(dx2, dx2, __hfma2(dy2, dy2, __hmul2(dz2, dz2)));
            g2 = (j == j2) ? inf2 : g2;

            INS4H(g1, a0, a1, a2, a3);
            INS4H(g2, c0, c1, c2, c3);
        }

        // epilogue: 2 chains x 2 halves, features in fp32
#pragma unroll
        for (int c = 0; c < 2; ++c) {
            const int jj = c ? j2 : j1;
            if (jj < J_DIM) {                // skip dummy chain (j1==12 -> j2==25)
                const __half2 m0 = c ? c0 : a0;
                const __half2 m1 = c ? c1 : a1;
                const __half2 m2 = c ? c2 : a2;
                const __half2 m3 = c ? c3 : a3;

                float S1 = 0.f, S2 = 0.f, S3 = 0.f, S4 = 0.f;
                float V2 = 0.f, V3 = 0.f, V4 = 0.f;
#pragma unroll
                for (int h = 0; h < 2; ++h) {
                    const float q0 = h ? __high2float(m0) : __low2float(m0);
                    const float q1 = h ? __high2float(m1) : __low2float(m1);
                    const float q2 = h ? __high2float(m2) : __low2float(m2);
                    const float q3 = h ? __high2float(m3) : __low2float(m3);

                    const float d1 = asqrt(q0);
                    const float d2 = asqrt(q1);
                    const float d3 = asqrt(q2);
                    const float d4 = asqrt(q3);

                    const float s2 = fabsf(d2 - d1) * 0.70710678118654752f;
                    const float a3f = (d1 + d2 + d3) * (1.0f / 3.0f);
                    const float e1 = d1 - a3f, e2 = d2 - a3f, e3 = d3 - a3f;
                    const float s3 = asqrt(fmaf(e1, e1, fmaf(e2, e2, e3 * e3)) * 0.5f);
                    const float a4f = (d1 + d2 + d3 + d4) * 0.25f;
                    const float g1f = d1 - a4f, g2f = d2 - a4f,
                                g3f = d3 - a4f, g4f = d4 - a4f;
                    const float s4 = asqrt(fmaf(g1f, g1f,
                                           fmaf(g2f, g2f,
                                            fmaf(g3f, g3f, g4f * g4f)))
                                           * (1.0f / 3.0f));

                    S1 += d1; S2 += d2; S3 += d3; S4 += d4;
                    V2 += s2; V3 += s3; V4 += s4;
                }
                float* sp = &spart[jj * NACC];
                atomicAdd(&sp[0], S1);
                atomicAdd(&sp[1], S2);
                atomicAdd(&sp[2], S3);
                atomicAdd(&sp[3], S4);
                atomicAdd(&sp[4], V2);
                atomicAdd(&sp[5], V3);
                atomicAdd(&sp[6], V4);
            }
        }
    }
    __syncthreads();

    // publish this split's partial
    if (tid < PARTB) g_scratch[b][s][tid] = spart[tid];
    __threadfence();
    __syncthreads();

    if (tid == 0) {
        unsigned old = atomicAdd(&g_ticket[b], 1u);
        s_last = (old == SPLIT - 1);
        if (s_last) g_ticket[b] = 0;   // self-reset for next graph replay
    }
    __syncthreads();

    if (s_last) {
        __threadfence();
        if (tid < PARTB) {
            float sum = 0.0f;
#pragma unroll
            for (int k = 0; k < SPLIT; ++k)
                sum += g_scratch[b][k][tid];
            sfin[tid] = sum;
        }
        __syncthreads();
        for (int i = tid; i < OUTB; i += TPB) {
            const int j = i / FEAT;
            const int f = i % FEAT;
            const float* a = &sfin[j * NACC];
            const float t1 = a[0], t2 = a[1], t3 = a[2], t4 = a[3];
            float v;
            switch (f) {
                case 0: v = (t1 + t2) * 0.5f;               break;
                case 1: v = a[4];                           break;
                case 2: v = t1;                             break;
                case 3: v = (t1 + t2 + t3) * (1.f / 3.f);   break;
                case 4: v = a[5];                           break;
                case 5: v = t1;                             break;
                case 6: v = (t1 + t2 + t3 + t4) * 0.25f;    break;
                case 7: v = a[6];                           break;
                default: v = t1;                            break;
            }
            out[(size_t)b * OUTB + i] = v * (1.0f / (float)T_DIM);
        }
    }
}

extern "C" void kernel_launch(void* const* d_in, const int* in_sizes, int n_in,
                              void* d_out, int out_size) {
    const float* x = (const float*)d_in[0];
    float* out = (float*)d_out;
    dim3 grid(B_DIM, SPLIT);
    knn_feat_kernel<<<grid, TPB>>>(x, out);
}

// round 12
// speedup vs baseline: 1.1000x; 1.1000x over previous
#include <cuda_runtime.h>
#include <cuda_fp16.h>
#include <math.h>
#include <float.h>

#define B_DIM  256
#define T_DIM  150
#define J_DIM  25
#define JW     (2 * J_DIM)              // duplicated row width (50 cols)
#define FEAT   9
#define NACC   7
#define SPLIT  5
#define TCHUNK (T_DIM / SPLIT)          // 30 timesteps per block
#define NPAIR  (TCHUNK / 2)             // 15 timestep-pairs
#define TPB    (NPAIR * J_DIM)          // 375 threads; thread = (pair, joint)
#define ITEMS  (TCHUNK * J_DIM)         // 750
#define OUTB   (J_DIM * FEAT)           // 225
#define PARTB  (J_DIM * NACC)           // 175

__device__ float    g_scratch[B_DIM][SPLIT][PARTB];
__device__ unsigned g_ticket[B_DIM];    // zero-init; self-resetting

__device__ __forceinline__ float asqrt(float x) {
    float r;
    asm("sqrt.approx.f32 %0, %1;" : "=f"(r) : "f"(x));
    return r;
}

__global__ __launch_bounds__(TPB)
void knn_feat_kernel(const float* __restrict__ x, float* __restrict__ out) {
    // packed positions, duplicated row: [pair][joint c] = joint (c%25)
    // entry = {x2, y2, z2, pad}, half2 lanes = (t, t+15)
    __shared__ uint4 sq[NPAIR][JW];          // 15*50*16 = 12000 B
    __shared__ float spart[PARTB];
    __shared__ float sfin[PARTB];
    __shared__ bool  s_last;

    const int b   = blockIdx.x;
    const int s   = blockIdx.y;
    const int tid = threadIdx.x;

    // build packed half2 SMEM tile (write each item to both duplicate columns)
    const float* xb = x + ((size_t)b * T_DIM + s * TCHUNK) * (J_DIM * 3);
#pragma unroll
    for (int r = 0; r < 2; ++r) {
        int i = tid + r * TPB;               // 0..749 : (t, j) item
        int t = i / J_DIM;
        int j = i % J_DIM;
        int pr = t % NPAIR;
        int hi = t / NPAIR;
        __half hx = __float2half_rn(xb[3 * i + 0]);
        __half hy = __float2half_rn(xb[3 * i + 1]);
        __half hz = __float2half_rn(xb[3 * i + 2]);
        __half* b0 = (__half*)&sq[pr][j];
        b0[0 * 2 + hi] = hx;
        b0[1 * 2 + hi] = hy;
        b0[2 * 2 + hi] = hz;
        __half* b1 = (__half*)&sq[pr][j + J_DIM];
        b1[0 * 2 + hi] = hx;
        b1[1 * 2 + hi] = hy;
        b1[2 * 2 + hi] = hz;
    }
    if (tid < PARTB) spart[tid] = 0.0f;
    __syncthreads();

    const int jidx = tid % J_DIM;            // this thread's joint
    const int pr   = tid / J_DIM;            // timestep pair (0..14)

    // query position (both halves) — one LDS.128
    const uint4 P = sq[pr][jidx];
    const __half2 px = *(const __half2*)&P.x;
    const __half2 py = *(const __half2*)&P.y;
    const __half2 pz = *(const __half2*)&P.z;

    const unsigned inf_bits = 0x7C007C00u;   // (+inf, +inf)
    const __half2 inf2 = *(const __half2*)&inf_bits;

    __half2 m0 = inf2, m1 = inf2, m2 = inf2, m3 = inf2;

    // rotated candidate loop: j = jidx + o, o = 1..24  (self excluded by construction)
    const uint4* __restrict__ qrow = &sq[pr][jidx];
#pragma unroll
    for (int o = 1; o < J_DIM; ++o) {
        const uint4 Q = qrow[o];             // imm-offset LDS.128
        const __half2 qx = *(const __half2*)&Q.x;
        const __half2 qy = *(const __half2*)&Q.y;
        const __half2 qz = *(const __half2*)&Q.z;

        const __half2 dx = __hsub2(px, qx);
        const __half2 dy = __hsub2(py, qy);
        const __half2 dz = __hsub2(pz, qz);
        __half2 g = __hfma2(dx, dx, __hfma2(dy, dy, __hmul2(dz, dz)));

        __half2 h;
        h = __hmax2(g, m0); m0 = __hmin2(g, m0); g = h;
        h = __hmax2(g, m1); m1 = __hmin2(g, m1); g = h;
        h = __hmax2(g, m2); m2 = __hmin2(g, m2); g = h;
        m3 = __hmin2(g, m3);
    }

    // epilogue: two chains (lo/hi halves), features in fp32, summed
    float S1 = 0.f, S2 = 0.f, S3 = 0.f, S4 = 0.f;
    float V2 = 0.f, V3 = 0.f, V4 = 0.f;

#pragma unroll
    for (int h = 0; h < 2; ++h) {
        const float q0 = h ? __high2float(m0) : __low2float(m0);
        const float q1 = h ? __high2float(m1) : __low2float(m1);
        const float q2 = h ? __high2float(m2) : __low2float(m2);
        const float q3 = h ? __high2float(m3) : __low2float(m3);

        const float d1 = asqrt(q0);
        const float d2 = asqrt(q1);
        const float d3 = asqrt(q2);
        const float d4 = asqrt(q3);

        const float s2 = fabsf(d2 - d1) * 0.70710678118654752f;
        const float a3 = (d1 + d2 + d3) * (1.0f / 3.0f);
        const float e1 = d1 - a3, e2 = d2 - a3, e3 = d3 - a3;
        const float s3 = asqrt(fmaf(e1, e1, fmaf(e2, e2, e3 * e3)) * 0.5f);
        const float a4 = (d1 + d2 + d3 + d4) * 0.25f;
        const float g1 = d1 - a4, g2 = d2 - a4, g3 = d3 - a4, g4 = d4 - a4;
        const float s4 = asqrt(fmaf(g1, g1, fmaf(g2, g2, fmaf(g3, g3, g4 * g4)))
                               * (1.0f / 3.0f));

        S1 += d1; S2 += d2; S3 += d3; S4 += d4;
        V2 += s2; V3 += s3; V4 += s4;
    }

    // combine the 15 threads sharing each joint (SMEM atomics)
    atomicAdd(&spart[jidx * NACC + 0], S1);
    atomicAdd(&spart[jidx * NACC + 1], S2);
    atomicAdd(&spart[jidx * NACC + 2], S3);
    atomicAdd(&spart[jidx * NACC + 3], S4);
    atomicAdd(&spart[jidx * NACC + 4], V2);
    atomicAdd(&spart[jidx * NACC + 5], V3);
    atomicAdd(&spart[jidx * NACC + 6], V4);
    __syncthreads();

    // publish this split's partial
    if (tid < PARTB) g_scratch[b][s][tid] = spart[tid];
    __threadfence();
    __syncthreads();

    if (tid == 0) {
        unsigned old = atomicAdd(&g_ticket[b], 1u);
        s_last = (old == SPLIT - 1);
        if (s_last) g_ticket[b] = 0;   // self-reset for next graph replay
    }
    __syncthreads();

    if (s_last) {
        __threadfence();
        if (tid < PARTB) {
            float sum = 0.0f;
#pragma unroll
            for (int k = 0; k < SPLIT; ++k)
                sum += g_scratch[b][k][tid];
            sfin[tid] = sum;
        }
        __syncthreads();
        if (tid < OUTB) {
            const int j = tid / FEAT;
            const int f = tid % FEAT;
            const float* a = &sfin[j * NACC];
            const float t1 = a[0], t2 = a[1], t3 = a[2], t4 = a[3];
            float v;
            switch (f) {
                case 0: v = (t1 + t2) * 0.5f;               break;
                case 1: v = a[4];                           break;
                case 2: v = t1;                             break;
                case 3: v = (t1 + t2 + t3) * (1.f / 3.f);   break;
                case 4: v = a[5];                           break;
                case 5: v = t1;                             break;
                case 6: v = (t1 + t2 + t3 + t4) * 0.25f;    break;
                case 7: v = a[6];                           break;
                default: v = t1;                            break;
            }
            out[(size_t)b * OUTB + tid] = v * (1.0f / (float)T_DIM);
        }
    }
}

extern "C" void kernel_launch(void* const* d_in, const int* in_sizes, int n_in,
                              void* d_out, int out_size) {
    const float* x = (const float*)d_in[0];
    float* out = (float*)d_out;
    dim3 grid(B_DIM, SPLIT);
    knn_feat_kernel<<<grid, TPB>>>(x, out);
}